// round 15
// baseline (speedup 1.0000x reference)
#include <cuda_runtime.h>
#include <cuda_bf16.h>

// ---------------------------------------------------------------------------
// MultiHeadedAttention: B=4, S=2048, D_MODEL=1024, H=16, DK=DV=64
// Round 15: attention 128 -> 256 threads (8 warps x 16-row tiles): regs
//           halved, 16 warps/SM for latency hiding. GEMMs/LN = R13/14.
// ---------------------------------------------------------------------------

#define NEGV (-1e9f)
#define MINIT (-1e38f)

__device__ __nv_bfloat16 g_q[4 * 16 * 2048 * 64];
__device__ __nv_bfloat16 g_k[4 * 16 * 2048 * 64];
__device__ __nv_bfloat16 g_v[4 * 16 * 2048 * 64];   // V^T per head [B,H,64,2048]
__device__ float g_attn[8192 * 1024];
__device__ float g_y[8192 * 1024];

__device__ __forceinline__ void mma_tf32(float c[4], const unsigned a[4],
                                         const unsigned b[2]) {
    asm volatile(
        "mma.sync.aligned.m16n8k8.row.col.f32.tf32.tf32.f32 "
        "{%0,%1,%2,%3}, {%4,%5,%6,%7}, {%8,%9}, {%0,%1,%2,%3};"
        : "+f"(c[0]), "+f"(c[1]), "+f"(c[2]), "+f"(c[3])
        : "r"(a[0]), "r"(a[1]), "r"(a[2]), "r"(a[3]), "r"(b[0]), "r"(b[1]));
}

__device__ __forceinline__ void mma_bf16(float c[4], const unsigned a[4],
                                         const unsigned b[2]) {
    asm volatile(
        "mma.sync.aligned.m16n8k16.row.col.f32.bf16.bf16.f32 "
        "{%0,%1,%2,%3}, {%4,%5,%6,%7}, {%8,%9}, {%0,%1,%2,%3};"
        : "+f"(c[0]), "+f"(c[1]), "+f"(c[2]), "+f"(c[3])
        : "r"(a[0]), "r"(a[1]), "r"(a[2]), "r"(a[3]), "r"(b[0]), "r"(b[1]));
}

__device__ __forceinline__ void ldsm4(unsigned& r0, unsigned& r1,
                                      unsigned& r2, unsigned& r3,
                                      const void* p) {
    unsigned a = (unsigned)__cvta_generic_to_shared(p);
    asm volatile(
        "ldmatrix.sync.aligned.m8n8.x4.shared.b16 {%0,%1,%2,%3}, [%4];"
        : "=r"(r0), "=r"(r1), "=r"(r2), "=r"(r3) : "r"(a));
}

__device__ __forceinline__ float ex2(float x) {
    float y;
    asm("ex2.approx.f32 %0, %1;" : "=f"(y) : "f"(x));
    return y;
}

__device__ __forceinline__ unsigned pack_bf16(float lo, float hi) {
    unsigned u;
    asm("cvt.rn.bf16x2.f32 %0, %1, %2;" : "=r"(u) : "f"(hi), "f"(lo));
    return u;
}

__device__ __forceinline__ void cpa16(void* sptr, const void* gptr) {
    unsigned s = (unsigned)__cvta_generic_to_shared(sptr);
    asm volatile("cp.async.cg.shared.global [%0], [%1], 16;"
                 :: "r"(s), "l"(gptr));
}
#define CP_COMMIT() asm volatile("cp.async.commit_group;")
#define CP_WAIT1()  asm volatile("cp.async.wait_group 1;")
#define CP_WAIT0()  asm volatile("cp.async.wait_group 0;")

// ---------------------------------------------------------------------------
// tf32 GEMM body (R13): 128x128 tile, k-tile 32, cp.async 3-stage pipeline.
// ---------------------------------------------------------------------------
#define GA_SZ (128 * 36)
#define GB_SZ (32 * 132)
#define GSTAGES 3
#define GEMM_SMEM (GSTAGES * (GA_SZ + GB_SZ) * 4)

__device__ __forceinline__ void gemm_body(
    const float* __restrict__ A, const float* __restrict__ B,
    void* __restrict__ Cv, int M, int N, int K, int mode,
    unsigned* As, unsigned* Bs)
{
    int tid = threadIdx.x;
    int wid = tid >> 5, lane = tid & 31;
    int r = lane >> 2, c = lane & 3, g = lane >> 2;
    int m0 = blockIdx.y * 128, n0 = blockIdx.x * 128;
    int wm = (wid & 1) * 64, wn = (wid >> 1) * 32;

    int arow[4], acol[4], brow[4], bcol[4];
#pragma unroll
    for (int i = 0; i < 4; i++) {
        int lin = tid + i * 256;
        arow[i] = lin >> 3;  acol[i] = (lin & 7) << 2;
        brow[i] = lin >> 5;  bcol[i] = (lin & 31) << 2;
    }

    float acc[4][4][4];
#pragma unroll
    for (int mt = 0; mt < 4; mt++)
#pragma unroll
        for (int nt = 0; nt < 4; nt++)
#pragma unroll
            for (int i = 0; i < 4; i++) acc[mt][nt][i] = 0.f;

    int ktiles = K >> 5;

#pragma unroll
    for (int st = 0; st < 2; st++) {
        int k0 = st * 32;
        unsigned* Asx = As + st * GA_SZ;
        unsigned* Bsx = Bs + st * GB_SZ;
#pragma unroll
        for (int i = 0; i < 4; i++) {
            cpa16(&Asx[arow[i] * 36 + acol[i]],
                  &A[(size_t)(m0 + arow[i]) * K + k0 + acol[i]]);
            cpa16(&Bsx[brow[i] * 132 + bcol[i]],
                  &B[(size_t)(k0 + brow[i]) * N + n0 + bcol[i]]);
        }
        CP_COMMIT();
    }

    for (int it = 0; it < ktiles; it++) {
        CP_WAIT1();
        __syncthreads();

        if (it + 2 < ktiles) {
            int st = (it + 2) % GSTAGES;
            int k0 = (it + 2) * 32;
            unsigned* Asx = As + st * GA_SZ;
            unsigned* Bsx = Bs + st * GB_SZ;
#pragma unroll
            for (int i = 0; i < 4; i++) {
                cpa16(&Asx[arow[i] * 36 + acol[i]],
                      &A[(size_t)(m0 + arow[i]) * K + k0 + acol[i]]);
                cpa16(&Bsx[brow[i] * 132 + bcol[i]],
                      &B[(size_t)(k0 + brow[i]) * N + n0 + bcol[i]]);
            }
        }
        CP_COMMIT();

        const unsigned* Asx = As + (it % GSTAGES) * GA_SZ;
        const unsigned* Bsx = Bs + (it % GSTAGES) * GB_SZ;
#pragma unroll
        for (int ks = 0; ks < 4; ks++) {
            int k8 = ks * 8;
            unsigned ua[4][4], ub[4][2];
#pragma unroll
            for (int mt = 0; mt < 4; mt++) {
                int rr = wm + mt * 16 + r;
                ua[mt][0] = Asx[rr * 36 + k8 + c];
                ua[mt][1] = Asx[(rr + 8) * 36 + k8 + c];
                ua[mt][2] = Asx[rr * 36 + k8 + c + 4];
                ua[mt][3] = Asx[(rr + 8) * 36 + k8 + c + 4];
            }
#pragma unroll
            for (int nt = 0; nt < 4; nt++) {
                int cn = wn + nt * 8 + g;
                ub[nt][0] = Bsx[(k8 + c) * 132 + cn];
                ub[nt][1] = Bsx[(k8 + c + 4) * 132 + cn];
            }
#pragma unroll
            for (int mt = 0; mt < 4; mt++)
#pragma unroll
                for (int nt = 0; nt < 4; nt++)
                    mma_tf32(acc[mt][nt], ua[mt], ub[nt]);
        }
        __syncthreads();
    }

#pragma unroll
    for (int mt = 0; mt < 4; mt++) {
#pragma unroll
        for (int nt = 0; nt < 4; nt++) {
            int rr = m0 + wm + mt * 16 + r;
            int cc = n0 + wn + nt * 8 + 2 * c;
            float* a4 = acc[mt][nt];
            if (mode == 0) {
                float* C = (float*)Cv;
                *(float2*)&C[(size_t)rr * N + cc] = make_float2(a4[0], a4[1]);
                *(float2*)&C[(size_t)(rr + 8) * N + cc] = make_float2(a4[2], a4[3]);
            } else if (mode == 1) {
                __nv_bfloat16* C = (__nv_bfloat16*)Cv;
                int b = rr >> 11, s = rr & 2047;
                int h = cc >> 6, d = cc & 63;
                size_t idx = (((size_t)(b * 16 + h) * 2048 + s) << 6) + d;
                *(__nv_bfloat162*)&C[idx] = __floats2bfloat162_rn(a4[0], a4[1]);
                int b2 = (rr + 8) >> 11, s2 = (rr + 8) & 2047;
                size_t idx2 = (((size_t)(b2 * 16 + h) * 2048 + s2) << 6) + d;
                *(__nv_bfloat162*)&C[idx2] = __floats2bfloat162_rn(a4[2], a4[3]);
            } else {  // bf16 V^T [B,H,64,2048]
                __nv_bfloat16* C = (__nv_bfloat16*)Cv;
                int b = rr >> 11, s = rr & 2047;
                int h = cc >> 6, d = cc & 63;
                size_t base = ((size_t)(b * 16 + h) * 64 + d) * 2048;
                C[base + s] = __float2bfloat16_rn(a4[0]);
                C[base + 2048 + s] = __float2bfloat16_rn(a4[1]);
                int b2 = (rr + 8) >> 11, s2 = (rr + 8) & 2047;
                size_t base2 = ((size_t)(b2 * 16 + h) * 64 + d) * 2048;
                C[base2 + s2] = __float2bfloat16_rn(a4[2]);
                C[base2 + 2048 + s2] = __float2bfloat16_rn(a4[3]);
            }
        }
    }
}

__global__ void __launch_bounds__(256) gemm_proj(
    const float* __restrict__ Aq, const float* __restrict__ Ak,
    const float* __restrict__ Av,
    const float* __restrict__ Bq, const float* __restrict__ Bk,
    const float* __restrict__ Bv,
    __nv_bfloat16* q, __nv_bfloat16* k, __nv_bfloat16* v)
{
    extern __shared__ unsigned gsm[];
    int z = blockIdx.z;
    const float* A = (z == 0) ? Aq : (z == 1) ? Ak : Av;
    const float* B = (z == 0) ? Bq : (z == 1) ? Bk : Bv;
    void* C = (z == 0) ? (void*)q : (z == 1) ? (void*)k : (void*)v;
    int mode = (z == 2) ? 2 : 1;
    gemm_body(A, B, C, 8192, 1024, 1024, mode, gsm, gsm + GSTAGES * GA_SZ);
}

__global__ void __launch_bounds__(256) gemm_out(
    const float* __restrict__ A, const float* __restrict__ B,
    float* __restrict__ C)
{
    extern __shared__ unsigned gsm[];
    gemm_body(A, B, C, 8192, 1024, 1024, 0, gsm, gsm + GSTAGES * GA_SZ);
}

// ---------------------------------------------------------------------------
// Flash attention: bf16 mma + ldmatrix, cp.async K/V double-buffer.
// grid (S/128, H, B), 256 threads (8 warps, warp 16 rows x 64 cols).
// SMEM bf16 stride 72: Qs[128] K0[64] K1[64] V0[64] V1[64] Ps[128] = 72 KB
// ---------------------------------------------------------------------------
#define SQ 72
#define ATTN_SMEM ((128 + 2 * 64 + 2 * 64 + 128) * SQ * 2)

__global__ void __launch_bounds__(256, 2) attn_tc(
    const __nv_bfloat16* __restrict__ Q, const __nv_bfloat16* __restrict__ Kg,
    const __nv_bfloat16* __restrict__ Vt, const int* __restrict__ mask,
    float* __restrict__ O)
{
    extern __shared__ __align__(16) __nv_bfloat16 smb[];
    __nv_bfloat16* Qs = smb;                       // 128 x 72
    __nv_bfloat16* Kst[2] = {Qs + 128 * SQ, Qs + (128 + 64) * SQ};
    __nv_bfloat16* Vst[2] = {Qs + (128 + 128) * SQ, Qs + (128 + 192) * SQ};
    __nv_bfloat16* Ps = Qs + (128 + 256) * SQ;     // 128 x 72

    int tid = threadIdx.x;
    int wid = tid >> 5, lane = tid & 31;
    int r = lane >> 2, c = lane & 3;
    int qt = blockIdx.x, h = blockIdx.y, b = blockIdx.z;
    int qbase = qt * 128;
    int wm = wid * 16;                             // warp owns 16 rows

    const float SC = 0.125f * 1.44269504088896f;

    const __nv_bfloat16* qp  = Q  + (((size_t)(b * 16 + h) * 2048 + qbase) << 6);
    const __nv_bfloat16* kp0 = Kg + (((size_t)(b * 16 + h) * 2048) << 6);
    const __nv_bfloat16* vt0 = Vt + ((size_t)(b * 16 + h) * 64) * 2048;

    const int* mrow[2];
#pragma unroll
    for (int hf = 0; hf < 2; hf++)
        mrow[hf] = mask +
            ((size_t)(b * 2048 + qbase + wm + r + hf * 8)) * 2048 + 2 * c;

    // staging indices (256 threads)
    int qrow = tid >> 3, qch = (tid & 7) << 3;     // Q: 32 rows/pass x 4
    int srow = tid >> 3, sch = (tid & 7) << 3;     // K/V: 32 rows/pass x 2

    // stage Q tile + first K/V tile (all async)
#pragma unroll
    for (int i = 0; i < 4; i++) {
        int row = qrow + i * 32;
        cpa16(&Qs[row * SQ + qch], &qp[(size_t)row * 64 + qch]);
    }
#pragma unroll
    for (int i = 0; i < 2; i++) {
        int row = srow + i * 32;
        cpa16(&Kst[0][row * SQ + sch], &kp0[(size_t)row * 64 + sch]);
        cpa16(&Vst[0][row * SQ + sch], &vt0[(size_t)row * 2048 + sch]);
    }
    CP_COMMIT();

    int la_row = lane & 15;
    int la_col = (lane >> 4) << 3;
    int lb_row = ((lane >> 4) << 3) + (lane & 7);
    int lb_col = ((lane >> 3) & 1) << 3;

    float m_[2] = {MINIT, MINIT}, l_[2] = {0.f, 0.f};

    float oacc[8][4];
#pragma unroll
    for (int nt = 0; nt < 8; nt++)
#pragma unroll
        for (int i = 0; i < 4; i++) oacc[nt][i] = 0.f;

    for (int it = 0; it < 32; it++) {
        int kb = it * 64;
        CP_WAIT0();
        __syncthreads();

        if (it + 1 < 32) {
            int kb2 = kb + 64;
            __nv_bfloat16* Kn = Kst[(it + 1) & 1];
            __nv_bfloat16* Vn = Vst[(it + 1) & 1];
#pragma unroll
            for (int i = 0; i < 2; i++) {
                int row = srow + i * 32;
                cpa16(&Kn[row * SQ + sch], &kp0[(size_t)(kb2 + row) * 64 + sch]);
                cpa16(&Vn[row * SQ + sch], &vt0[(size_t)row * 2048 + kb2 + sch]);
            }
        }
        CP_COMMIT();

        const __nv_bfloat16* Ks = Kst[it & 1];
        const __nv_bfloat16* Vs = Vst[it & 1];

        // ---- S = Q K^T ----
        float sacc[8][4];
#pragma unroll
        for (int nt = 0; nt < 8; nt++)
#pragma unroll
            for (int i = 0; i < 4; i++) sacc[nt][i] = 0.f;

#pragma unroll
        for (int ks = 0; ks < 4; ks++) {
            int k16 = ks * 16;
            unsigned ua[4], ubs[8][2];
            ldsm4(ua[0], ua[1], ua[2], ua[3],
                  &Qs[(wm + la_row) * SQ + k16 + la_col]);
#pragma unroll
            for (int nt2 = 0; nt2 < 4; nt2++) {
                unsigned r0, r1, r2, r3;
                ldsm4(r0, r1, r2, r3,
                      &Ks[(nt2 * 16 + lb_row) * SQ + k16 + lb_col]);
                ubs[nt2 * 2][0] = r0;  ubs[nt2 * 2][1] = r1;
                ubs[nt2 * 2 + 1][0] = r2;  ubs[nt2 * 2 + 1][1] = r3;
            }
#pragma unroll
            for (int nt = 0; nt < 8; nt++)
                mma_bf16(sacc[nt], ua, ubs[nt]);
        }

        // ---- mask + online softmax (log2 domain) ----
        {
            float mx0 = m_[0], mx1 = m_[1];
#pragma unroll
            for (int nt = 0; nt < 8; nt++) {
                int2 mk0 = *(const int2*)(mrow[0] + kb + nt * 8);
                int2 mk1 = *(const int2*)(mrow[1] + kb + nt * 8);
                float s0 = mk0.x ? sacc[nt][0] * SC : NEGV;
                float s1 = mk0.y ? sacc[nt][1] * SC : NEGV;
                float s2 = mk1.x ? sacc[nt][2] * SC : NEGV;
                float s3 = mk1.y ? sacc[nt][3] * SC : NEGV;
                sacc[nt][0] = s0; sacc[nt][1] = s1;
                sacc[nt][2] = s2; sacc[nt][3] = s3;
                mx0 = fmaxf(mx0, fmaxf(s0, s1));
                mx1 = fmaxf(mx1, fmaxf(s2, s3));
            }
            mx0 = fmaxf(mx0, __shfl_xor_sync(0xffffffffu, mx0, 1));
            mx0 = fmaxf(mx0, __shfl_xor_sync(0xffffffffu, mx0, 2));
            mx1 = fmaxf(mx1, __shfl_xor_sync(0xffffffffu, mx1, 1));
            mx1 = fmaxf(mx1, __shfl_xor_sync(0xffffffffu, mx1, 2));

            float al0 = ex2(m_[0] - mx0);
            float al1 = ex2(m_[1] - mx1);
            float sum0 = 0.f, sum1 = 0.f;
            int rr = wm + r;
#pragma unroll
            for (int nt = 0; nt < 8; nt++) {
                float p0 = ex2(sacc[nt][0] - mx0);
                float p1 = ex2(sacc[nt][1] - mx0);
                float p2 = ex2(sacc[nt][2] - mx1);
                float p3 = ex2(sacc[nt][3] - mx1);
                sum0 += p0 + p1;
                sum1 += p2 + p3;
                *(unsigned*)&Ps[rr * SQ + nt * 8 + 2 * c] = pack_bf16(p0, p1);
                *(unsigned*)&Ps[(rr + 8) * SQ + nt * 8 + 2 * c] = pack_bf16(p2, p3);
            }
            sum0 += __shfl_xor_sync(0xffffffffu, sum0, 1);
            sum0 += __shfl_xor_sync(0xffffffffu, sum0, 2);
            sum1 += __shfl_xor_sync(0xffffffffu, sum1, 1);
            sum1 += __shfl_xor_sync(0xffffffffu, sum1, 2);

            m_[0] = mx0; m_[1] = mx1;
            l_[0] = l_[0] * al0 + sum0;
            l_[1] = l_[1] * al1 + sum1;
#pragma unroll
            for (int nt = 0; nt < 8; nt++) {
                oacc[nt][0] *= al0; oacc[nt][1] *= al0;
                oacc[nt][2] *= al1; oacc[nt][3] *= al1;
            }
        }
        __syncwarp();   // Ps rows are warp-private

        // ---- O += P V ----
#pragma unroll
        for (int ks = 0; ks < 4; ks++) {
            int k16 = ks * 16;
            unsigned ua[4], ubs[8][2];
            ldsm4(ua[0], ua[1], ua[2], ua[3],
                  &Ps[(wm + la_row) * SQ + k16 + la_col]);
#pragma unroll
            for (int nt2 = 0; nt2 < 4; nt2++) {
                unsigned r0, r1, r2, r3;
                ldsm4(r0, r1, r2, r3,
                      &Vs[(nt2 * 16 + lb_row) * SQ + k16 + lb_col]);
                ubs[nt2 * 2][0] = r0;  ubs[nt2 * 2][1] = r1;
                ubs[nt2 * 2 + 1][0] = r2;  ubs[nt2 * 2 + 1][1] = r3;
            }
#pragma unroll
            for (int nt = 0; nt < 8; nt++)
                mma_bf16(oacc[nt], ua, ubs[nt]);
        }
        __syncthreads();   // all warps done reading stage before overwrite
    }

    // final normalize + write [B,S,H*64] fp32
    {
        float l0 = 1.f / l_[0];
        float l1 = 1.f / l_[1];
        int rowg = qbase + wm + r;
#pragma unroll
        for (int nt = 0; nt < 8; nt++) {
            int cc = h * 64 + nt * 8 + 2 * c;
            *(float2*)&O[(size_t)(b * 2048 + rowg) * 1024 + cc] =
                make_float2(oacc[nt][0] * l0, oacc[nt][1] * l0);
            *(float2*)&O[(size_t)(b * 2048 + rowg + 8) * 1024 + cc] =
                make_float2(oacc[nt][2] * l1, oacc[nt][3] * l1);
        }
    }
}

// ---------------------------------------------------------------------------
// residual + LayerNorm
// ---------------------------------------------------------------------------
__global__ void __launch_bounds__(256) ln_kernel(
    const float* __restrict__ Y, const float* __restrict__ R,
    const float* __restrict__ g, const float* __restrict__ bt,
    float* __restrict__ out)
{
    __shared__ float red[2][8];
    int row = blockIdx.x;
    int tid = threadIdx.x;
    int lane = tid & 31, wid = tid >> 5;

    float4 y4 = ((const float4*)(Y + (size_t)row * 1024))[tid];
    float4 r4 = ((const float4*)(R + (size_t)row * 1024))[tid];
    float x0 = y4.x + r4.x, x1 = y4.y + r4.y, x2 = y4.z + r4.z, x3 = y4.w + r4.w;

    float sum = x0 + x1 + x2 + x3;
    float sq  = x0 * x0 + x1 * x1 + x2 * x2 + x3 * x3;
#pragma unroll
    for (int off = 16; off > 0; off >>= 1) {
        sum += __shfl_xor_sync(0xffffffff, sum, off);
        sq  += __shfl_xor_sync(0xffffffff, sq,  off);
    }
    if (lane == 0) { red[0][wid] = sum; red[1][wid] = sq; }
    __syncthreads();
    if (tid == 0) {
        float ts = 0.f, tq = 0.f;
#pragma unroll
        for (int w = 0; w < 8; w++) { ts += red[0][w]; tq += red[1][w]; }
        red[0][0] = ts; red[1][0] = tq;
    }
    __syncthreads();
    float mu  = red[0][0] * (1.f / 1024.f);
    float var = red[1][0] * (1.f / 1024.f) - mu * mu;
    float rstd = rsqrtf(var + 1e-6f);

    float4 g4 = ((const float4*)g)[tid];
    float4 b4 = ((const float4*)bt)[tid];
    float4 o;
    o.x = (x0 - mu) * rstd * g4.x + b4.x;
    o.y = (x1 - mu) * rstd * g4.y + b4.y;
    o.z = (x2 - mu) * rstd * g4.z + b4.z;
    o.w = (x3 - mu) * rstd * g4.w + b4.w;
    ((float4*)(out + (size_t)row * 1024))[tid] = o;
}

// ---------------------------------------------------------------------------
extern "C" void kernel_launch(void* const* d_in, const int* in_sizes, int n_in,
                              void* d_out, int out_size)
{
    const float* query = (const float*)d_in[0];
    const float* key   = (const float*)d_in[1];
    const float* value = (const float*)d_in[2];
    const int*   mask  = (const int*)d_in[3];
    const float* w_qs  = (const float*)d_in[4];
    const float* w_ks  = (const float*)d_in[5];
    const float* w_vs  = (const float*)d_in[6];
    const float* w_out = (const float*)d_in[7];
    const float* ln_g  = (const float*)d_in[8];
    const float* ln_b  = (const float*)d_in[9];
    float* out = (float*)d_out;

    __nv_bfloat16 *q, *k, *v;
    float *attn, *y;
    cudaGetSymbolAddress((void**)&q,    g_q);
    cudaGetSymbolAddress((void**)&k,    g_k);
    cudaGetSymbolAddress((void**)&v,    g_v);
    cudaGetSymbolAddress((void**)&attn, g_attn);
    cudaGetSymbolAddress((void**)&y,    g_y);

    cudaFuncSetAttribute(gemm_proj,
                         cudaFuncAttributeMaxDynamicSharedMemorySize, GEMM_SMEM);
    cudaFuncSetAttribute(gemm_out,
                         cudaFuncAttributeMaxDynamicSharedMemorySize, GEMM_SMEM);
    cudaFuncSetAttribute(attn_tc,
                         cudaFuncAttributeMaxDynamicSharedMemorySize, ATTN_SMEM);

    gemm_proj<<<dim3(8, 64, 3), 256, GEMM_SMEM>>>(
        query, key, value, w_qs, w_ks, w_vs, q, k, v);

    attn_tc<<<dim3(16, 16, 4), 256, ATTN_SMEM>>>(q, k, v, mask, attn);

    gemm_out<<<dim3(8, 64), 256, GEMM_SMEM>>>(attn, w_out, y);

    ln_kernel<<<8192, 256>>>(y, query, ln_g, ln_b, out);
}

// round 16
// speedup vs baseline: 1.0730x; 1.0730x over previous
#include <cuda_runtime.h>
#include <cuda_bf16.h>

// ---------------------------------------------------------------------------
// MultiHeadedAttention: B=4, S=2048, D_MODEL=1024, H=16, DK=DV=64
// Round 16: attention reverted to R14 (best: 4 warps x 32-row tiles).
//           GEMM warp tiles 64x32 -> 64x64 (4 warps, 128 thr): frag smem
//           traffic -33%, LDS/mma 1.5 -> 1.0, 2x MMA ILP per warp.
// ---------------------------------------------------------------------------

#define NEGV (-1e9f)
#define MINIT (-1e38f)

__device__ __nv_bfloat16 g_q[4 * 16 * 2048 * 64];
__device__ __nv_bfloat16 g_k[4 * 16 * 2048 * 64];
__device__ __nv_bfloat16 g_v[4 * 16 * 2048 * 64];   // V^T per head [B,H,64,2048]
__device__ float g_attn[8192 * 1024];
__device__ float g_y[8192 * 1024];

__device__ __forceinline__ void mma_tf32(float c[4], const unsigned a[4],
                                         const unsigned b[2]) {
    asm volatile(
        "mma.sync.aligned.m16n8k8.row.col.f32.tf32.tf32.f32 "
        "{%0,%1,%2,%3}, {%4,%5,%6,%7}, {%8,%9}, {%0,%1,%2,%3};"
        : "+f"(c[0]), "+f"(c[1]), "+f"(c[2]), "+f"(c[3])
        : "r"(a[0]), "r"(a[1]), "r"(a[2]), "r"(a[3]), "r"(b[0]), "r"(b[1]));
}

__device__ __forceinline__ void mma_bf16(float c[4], const unsigned a[4],
                                         const unsigned b[2]) {
    asm volatile(
        "mma.sync.aligned.m16n8k16.row.col.f32.bf16.bf16.f32 "
        "{%0,%1,%2,%3}, {%4,%5,%6,%7}, {%8,%9}, {%0,%1,%2,%3};"
        : "+f"(c[0]), "+f"(c[1]), "+f"(c[2]), "+f"(c[3])
        : "r"(a[0]), "r"(a[1]), "r"(a[2]), "r"(a[3]), "r"(b[0]), "r"(b[1]));
}

__device__ __forceinline__ void ldsm4(unsigned& r0, unsigned& r1,
                                      unsigned& r2, unsigned& r3,
                                      const void* p) {
    unsigned a = (unsigned)__cvta_generic_to_shared(p);
    asm volatile(
        "ldmatrix.sync.aligned.m8n8.x4.shared.b16 {%0,%1,%2,%3}, [%4];"
        : "=r"(r0), "=r"(r1), "=r"(r2), "=r"(r3) : "r"(a));
}

__device__ __forceinline__ float ex2(float x) {
    float y;
    asm("ex2.approx.f32 %0, %1;" : "=f"(y) : "f"(x));
    return y;
}

__device__ __forceinline__ unsigned pack_bf16(float lo, float hi) {
    unsigned u;
    asm("cvt.rn.bf16x2.f32 %0, %1, %2;" : "=r"(u) : "f"(hi), "f"(lo));
    return u;
}

__device__ __forceinline__ void cpa16(void* sptr, const void* gptr) {
    unsigned s = (unsigned)__cvta_generic_to_shared(sptr);
    asm volatile("cp.async.cg.shared.global [%0], [%1], 16;"
                 :: "r"(s), "l"(gptr));
}
#define CP_COMMIT() asm volatile("cp.async.commit_group;")
#define CP_WAIT1()  asm volatile("cp.async.wait_group 1;")
#define CP_WAIT0()  asm volatile("cp.async.wait_group 0;")

// ---------------------------------------------------------------------------
// tf32 GEMM body: 128x128 tile, k-tile 32, 128 threads (4 warps, 64x64 warp
// tiles, 2m x 2n), cp.async 3-stage pipeline, raw fp32 (HW tf32 truncation).
// ---------------------------------------------------------------------------
#define GA_SZ (128 * 36)
#define GB_SZ (32 * 132)
#define GSTAGES 3
#define GEMM_SMEM (GSTAGES * (GA_SZ + GB_SZ) * 4)

__device__ __forceinline__ void gemm_body(
    const float* __restrict__ A, const float* __restrict__ B,
    void* __restrict__ Cv, int M, int N, int K, int mode,
    unsigned* As, unsigned* Bs)
{
    int tid = threadIdx.x;
    int wid = tid >> 5, lane = tid & 31;
    int r = lane >> 2, c = lane & 3, g = lane >> 2;
    int m0 = blockIdx.y * 128, n0 = blockIdx.x * 128;
    int wm = (wid & 1) * 64, wn = (wid >> 1) * 64;

    int arow[8], acol[8], brow[8], bcol[8];
#pragma unroll
    for (int i = 0; i < 8; i++) {
        int lin = tid + i * 128;
        arow[i] = lin >> 3;  acol[i] = (lin & 7) << 2;    // A 128x32
        brow[i] = lin >> 5;  bcol[i] = (lin & 31) << 2;   // B 32x128
    }

    float acc[4][8][4];
#pragma unroll
    for (int mt = 0; mt < 4; mt++)
#pragma unroll
        for (int nt = 0; nt < 8; nt++)
#pragma unroll
            for (int i = 0; i < 4; i++) acc[mt][nt][i] = 0.f;

    int ktiles = K >> 5;

#pragma unroll
    for (int st = 0; st < 2; st++) {
        int k0 = st * 32;
        unsigned* Asx = As + st * GA_SZ;
        unsigned* Bsx = Bs + st * GB_SZ;
#pragma unroll
        for (int i = 0; i < 8; i++) {
            cpa16(&Asx[arow[i] * 36 + acol[i]],
                  &A[(size_t)(m0 + arow[i]) * K + k0 + acol[i]]);
            cpa16(&Bsx[brow[i] * 132 + bcol[i]],
                  &B[(size_t)(k0 + brow[i]) * N + n0 + bcol[i]]);
        }
        CP_COMMIT();
    }

    for (int it = 0; it < ktiles; it++) {
        CP_WAIT1();
        __syncthreads();

        if (it + 2 < ktiles) {
            int st = (it + 2) % GSTAGES;
            int k0 = (it + 2) * 32;
            unsigned* Asx = As + st * GA_SZ;
            unsigned* Bsx = Bs + st * GB_SZ;
#pragma unroll
            for (int i = 0; i < 8; i++) {
                cpa16(&Asx[arow[i] * 36 + acol[i]],
                      &A[(size_t)(m0 + arow[i]) * K + k0 + acol[i]]);
                cpa16(&Bsx[brow[i] * 132 + bcol[i]],
                      &B[(size_t)(k0 + brow[i]) * N + n0 + bcol[i]]);
            }
        }
        CP_COMMIT();

        const unsigned* Asx = As + (it % GSTAGES) * GA_SZ;
        const unsigned* Bsx = Bs + (it % GSTAGES) * GB_SZ;
#pragma unroll
        for (int ks = 0; ks < 4; ks++) {
            int k8 = ks * 8;
            unsigned ua[4][4], ub[8][2];
#pragma unroll
            for (int mt = 0; mt < 4; mt++) {
                int rr = wm + mt * 16 + r;
                ua[mt][0] = Asx[rr * 36 + k8 + c];
                ua[mt][1] = Asx[(rr + 8) * 36 + k8 + c];
                ua[mt][2] = Asx[rr * 36 + k8 + c + 4];
                ua[mt][3] = Asx[(rr + 8) * 36 + k8 + c + 4];
            }
#pragma unroll
            for (int nt = 0; nt < 8; nt++) {
                int cn = wn + nt * 8 + g;
                ub[nt][0] = Bsx[(k8 + c) * 132 + cn];
                ub[nt][1] = Bsx[(k8 + c + 4) * 132 + cn];
            }
#pragma unroll
            for (int mt = 0; mt < 4; mt++)
#pragma unroll
                for (int nt = 0; nt < 8; nt++)
                    mma_tf32(acc[mt][nt], ua[mt], ub[nt]);
        }
        __syncthreads();
    }

#pragma unroll
    for (int mt = 0; mt < 4; mt++) {
#pragma unroll
        for (int nt = 0; nt < 8; nt++) {
            int rr = m0 + wm + mt * 16 + r;
            int cc = n0 + wn + nt * 8 + 2 * c;
            float* a4 = acc[mt][nt];
            if (mode == 0) {
                float* C = (float*)Cv;
                *(float2*)&C[(size_t)rr * N + cc] = make_float2(a4[0], a4[1]);
                *(float2*)&C[(size_t)(rr + 8) * N + cc] = make_float2(a4[2], a4[3]);
            } else if (mode == 1) {
                __nv_bfloat16* C = (__nv_bfloat16*)Cv;
                int b = rr >> 11, s = rr & 2047;
                int h = cc >> 6, d = cc & 63;
                size_t idx = (((size_t)(b * 16 + h) * 2048 + s) << 6) + d;
                *(__nv_bfloat162*)&C[idx] = __floats2bfloat162_rn(a4[0], a4[1]);
                int b2 = (rr + 8) >> 11, s2 = (rr + 8) & 2047;
                size_t idx2 = (((size_t)(b2 * 16 + h) * 2048 + s2) << 6) + d;
                *(__nv_bfloat162*)&C[idx2] = __floats2bfloat162_rn(a4[2], a4[3]);
            } else {  // bf16 V^T [B,H,64,2048]
                __nv_bfloat16* C = (__nv_bfloat16*)Cv;
                int b = rr >> 11, s = rr & 2047;
                int h = cc >> 6, d = cc & 63;
                size_t base = ((size_t)(b * 16 + h) * 64 + d) * 2048;
                C[base + s] = __float2bfloat16_rn(a4[0]);
                C[base + 2048 + s] = __float2bfloat16_rn(a4[1]);
                int b2 = (rr + 8) >> 11, s2 = (rr + 8) & 2047;
                size_t base2 = ((size_t)(b2 * 16 + h) * 64 + d) * 2048;
                C[base2 + s2] = __float2bfloat16_rn(a4[2]);
                C[base2 + 2048 + s2] = __float2bfloat16_rn(a4[3]);
            }
        }
    }
}

__global__ void __launch_bounds__(128, 2) gemm_proj(
    const float* __restrict__ Aq, const float* __restrict__ Ak,
    const float* __restrict__ Av,
    const float* __restrict__ Bq, const float* __restrict__ Bk,
    const float* __restrict__ Bv,
    __nv_bfloat16* q, __nv_bfloat16* k, __nv_bfloat16* v)
{
    extern __shared__ unsigned gsm[];
    int z = blockIdx.z;
    const float* A = (z == 0) ? Aq : (z == 1) ? Ak : Av;
    const float* B = (z == 0) ? Bq : (z == 1) ? Bk : Bv;
    void* C = (z == 0) ? (void*)q : (z == 1) ? (void*)k : (void*)v;
    int mode = (z == 2) ? 2 : 1;
    gemm_body(A, B, C, 8192, 1024, 1024, mode, gsm, gsm + GSTAGES * GA_SZ);
}

__global__ void __launch_bounds__(128, 2) gemm_out(
    const float* __restrict__ A, const float* __restrict__ B,
    float* __restrict__ C)
{
    extern __shared__ unsigned gsm[];
    gemm_body(A, B, C, 8192, 1024, 1024, 0, gsm, gsm + GSTAGES * GA_SZ);
}

// ---------------------------------------------------------------------------
// Flash attention (R14, best): bf16 mma + ldmatrix, cp.async K/V double-
// buffer. grid (S/128, H, B), 128 threads (4 warps, 32 rows x 64 cols).
// SMEM bf16 stride 72: Qs[128] K0[64] K1[64] V0[64] V1[64] Ps[128] = 72 KB
// ---------------------------------------------------------------------------
#define SQ 72
#define ATTN_SMEM ((128 + 2 * 64 + 2 * 64 + 128) * SQ * 2)

__global__ void __launch_bounds__(128, 2) attn_tc(
    const __nv_bfloat16* __restrict__ Q, const __nv_bfloat16* __restrict__ Kg,
    const __nv_bfloat16* __restrict__ Vt, const int* __restrict__ mask,
    float* __restrict__ O)
{
    extern __shared__ __align__(16) __nv_bfloat16 smb[];
    __nv_bfloat16* Qs = smb;                       // 128 x 72
    __nv_bfloat16* Kst[2] = {Qs + 128 * SQ, Qs + (128 + 64) * SQ};
    __nv_bfloat16* Vst[2] = {Qs + (128 + 128) * SQ, Qs + (128 + 192) * SQ};
    __nv_bfloat16* Ps = Qs + (128 + 256) * SQ;     // 128 x 72

    int tid = threadIdx.x;
    int wid = tid >> 5, lane = tid & 31;
    int r = lane >> 2, c = lane & 3;
    int qt = blockIdx.x, h = blockIdx.y, b = blockIdx.z;
    int qbase = qt * 128;
    int wm = wid * 32;

    const float SC = 0.125f * 1.44269504088896f;

    const __nv_bfloat16* qp  = Q  + (((size_t)(b * 16 + h) * 2048 + qbase) << 6);
    const __nv_bfloat16* kp0 = Kg + (((size_t)(b * 16 + h) * 2048) << 6);
    const __nv_bfloat16* vt0 = Vt + ((size_t)(b * 16 + h) * 64) * 2048;

    const int* mrow[2][2];
#pragma unroll
    for (int mt = 0; mt < 2; mt++)
#pragma unroll
        for (int hf = 0; hf < 2; hf++)
            mrow[mt][hf] = mask +
                ((size_t)(b * 2048 + qbase + wm + mt * 16 + r + hf * 8)) * 2048 +
                2 * c;

    int srow = tid >> 3, sch = (tid & 7) << 3;

    // stage Q tile + first K/V tile
#pragma unroll
    for (int i = 0; i < 8; i++) {
        int lin = tid + i * 128;
        int row = lin >> 3, ch = (lin & 7) << 3;
        *(uint4*)&Qs[row * SQ + ch] = *(const uint4*)&qp[row * 64 + ch];
    }
#pragma unroll
    for (int i = 0; i < 4; i++) {
        int row = srow + i * 16;
        cpa16(&Kst[0][row * SQ + sch], &kp0[(size_t)row * 64 + sch]);
        cpa16(&Vst[0][row * SQ + sch], &vt0[(size_t)row * 2048 + sch]);
    }
    CP_COMMIT();

    int la_row = lane & 15;
    int la_col = (lane >> 4) << 3;
    int lb_row = ((lane >> 4) << 3) + (lane & 7);
    int lb_col = ((lane >> 3) & 1) << 3;

    float m_[2][2], l_[2][2];
#pragma unroll
    for (int mt = 0; mt < 2; mt++)
#pragma unroll
        for (int hf = 0; hf < 2; hf++) { m_[mt][hf] = MINIT; l_[mt][hf] = 0.f; }

    float oacc[2][8][4];
#pragma unroll
    for (int mt = 0; mt < 2; mt++)
#pragma unroll
        for (int nt = 0; nt < 8; nt++)
#pragma unroll
            for (int i = 0; i < 4; i++) oacc[mt][nt][i] = 0.f;

    for (int it = 0; it < 32; it++) {
        int kb = it * 64;
        CP_WAIT0();
        __syncthreads();

        if (it + 1 < 32) {
            int kb2 = kb + 64;
            __nv_bfloat16* Kn = Kst[(it + 1) & 1];
            __nv_bfloat16* Vn = Vst[(it + 1) & 1];
#pragma unroll
            for (int i = 0; i < 4; i++) {
                int row = srow + i * 16;
                cpa16(&Kn[row * SQ + sch], &kp0[(size_t)(kb2 + row) * 64 + sch]);
                cpa16(&Vn[row * SQ + sch], &vt0[(size_t)row * 2048 + kb2 + sch]);
            }
        }
        CP_COMMIT();

        const __nv_bfloat16* Ks = Kst[it & 1];
        const __nv_bfloat16* Vs = Vst[it & 1];

        // ---- S = Q K^T ----
        float sacc[2][8][4];
#pragma unroll
        for (int mt = 0; mt < 2; mt++)
#pragma unroll
            for (int nt = 0; nt < 8; nt++)
#pragma unroll
                for (int i = 0; i < 4; i++) sacc[mt][nt][i] = 0.f;

#pragma unroll
        for (int ks = 0; ks < 4; ks++) {
            int k16 = ks * 16;
            unsigned ua[2][4], ubs[8][2];
#pragma unroll
            for (int mt = 0; mt < 2; mt++)
                ldsm4(ua[mt][0], ua[mt][1], ua[mt][2], ua[mt][3],
                      &Qs[(wm + mt * 16 + la_row) * SQ + k16 + la_col]);
#pragma unroll
            for (int nt2 = 0; nt2 < 4; nt2++) {
                unsigned r0, r1, r2, r3;
                ldsm4(r0, r1, r2, r3,
                      &Ks[(nt2 * 16 + lb_row) * SQ + k16 + lb_col]);
                ubs[nt2 * 2][0] = r0;  ubs[nt2 * 2][1] = r1;
                ubs[nt2 * 2 + 1][0] = r2;  ubs[nt2 * 2 + 1][1] = r3;
            }
#pragma unroll
            for (int mt = 0; mt < 2; mt++)
#pragma unroll
                for (int nt = 0; nt < 8; nt++)
                    mma_bf16(sacc[mt][nt], ua[mt], ubs[nt]);
        }

        // ---- mask + online softmax (log2 domain) ----
#pragma unroll
        for (int mt = 0; mt < 2; mt++) {
            float mx0 = m_[mt][0], mx1 = m_[mt][1];
#pragma unroll
            for (int nt = 0; nt < 8; nt++) {
                int2 mk0 = *(const int2*)(mrow[mt][0] + kb + nt * 8);
                int2 mk1 = *(const int2*)(mrow[mt][1] + kb + nt * 8);
                float s0 = mk0.x ? sacc[mt][nt][0] * SC : NEGV;
                float s1 = mk0.y ? sacc[mt][nt][1] * SC : NEGV;
                float s2 = mk1.x ? sacc[mt][nt][2] * SC : NEGV;
                float s3 = mk1.y ? sacc[mt][nt][3] * SC : NEGV;
                sacc[mt][nt][0] = s0; sacc[mt][nt][1] = s1;
                sacc[mt][nt][2] = s2; sacc[mt][nt][3] = s3;
                mx0 = fmaxf(mx0, fmaxf(s0, s1));
                mx1 = fmaxf(mx1, fmaxf(s2, s3));
            }
            mx0 = fmaxf(mx0, __shfl_xor_sync(0xffffffffu, mx0, 1));
            mx0 = fmaxf(mx0, __shfl_xor_sync(0xffffffffu, mx0, 2));
            mx1 = fmaxf(mx1, __shfl_xor_sync(0xffffffffu, mx1, 1));
            mx1 = fmaxf(mx1, __shfl_xor_sync(0xffffffffu, mx1, 2));

            float al0 = ex2(m_[mt][0] - mx0);
            float al1 = ex2(m_[mt][1] - mx1);
            float sum0 = 0.f, sum1 = 0.f;
            int rr = wm + mt * 16 + r;
#pragma unroll
            for (int nt = 0; nt < 8; nt++) {
                float p0 = ex2(sacc[mt][nt][0] - mx0);
                float p1 = ex2(sacc[mt][nt][1] - mx0);
                float p2 = ex2(sacc[mt][nt][2] - mx1);
                float p3 = ex2(sacc[mt][nt][3] - mx1);
                sum0 += p0 + p1;
                sum1 += p2 + p3;
                *(unsigned*)&Ps[rr * SQ + nt * 8 + 2 * c] = pack_bf16(p0, p1);
                *(unsigned*)&Ps[(rr + 8) * SQ + nt * 8 + 2 * c] = pack_bf16(p2, p3);
            }
            sum0 += __shfl_xor_sync(0xffffffffu, sum0, 1);
            sum0 += __shfl_xor_sync(0xffffffffu, sum0, 2);
            sum1 += __shfl_xor_sync(0xffffffffu, sum1, 1);
            sum1 += __shfl_xor_sync(0xffffffffu, sum1, 2);

            m_[mt][0] = mx0; m_[mt][1] = mx1;
            l_[mt][0] = l_[mt][0] * al0 + sum0;
            l_[mt][1] = l_[mt][1] * al1 + sum1;
#pragma unroll
            for (int nt = 0; nt < 8; nt++) {
                oacc[mt][nt][0] *= al0; oacc[mt][nt][1] *= al0;
                oacc[mt][nt][2] *= al1; oacc[mt][nt][3] *= al1;
            }
        }
        __syncwarp();   // Ps rows are warp-private

        // ---- O += P V ----
#pragma unroll
        for (int ks = 0; ks < 4; ks++) {
            int k16 = ks * 16;
            unsigned ua[2][4], ubs[8][2];
#pragma unroll
            for (int mt = 0; mt < 2; mt++)
                ldsm4(ua[mt][0], ua[mt][1], ua[mt][2], ua[mt][3],
                      &Ps[(wm + mt * 16 + la_row) * SQ + k16 + la_col]);
#pragma unroll
            for (int nt2 = 0; nt2 < 4; nt2++) {
                unsigned r0, r1, r2, r3;
                ldsm4(r0, r1, r2, r3,
                      &Vs[(nt2 * 16 + lb_row) * SQ + k16 + lb_col]);
                ubs[nt2 * 2][0] = r0;  ubs[nt2 * 2][1] = r1;
                ubs[nt2 * 2 + 1][0] = r2;  ubs[nt2 * 2 + 1][1] = r3;
            }
#pragma unroll
            for (int mt = 0; mt < 2; mt++)
#pragma unroll
                for (int nt = 0; nt < 8; nt++)
                    mma_bf16(oacc[mt][nt], ua[mt], ubs[nt]);
        }
        __syncthreads();
    }

    // final normalize + write [B,S,H*64] fp32
#pragma unroll
    for (int mt = 0; mt < 2; mt++) {
        float l0 = 1.f / l_[mt][0];
        float l1 = 1.f / l_[mt][1];
        int rowg = qbase + wm + mt * 16 + r;
#pragma unroll
        for (int nt = 0; nt < 8; nt++) {
            int cc = h * 64 + nt * 8 + 2 * c;
            *(float2*)&O[(size_t)(b * 2048 + rowg) * 1024 + cc] =
                make_float2(oacc[mt][nt][0] * l0, oacc[mt][nt][1] * l0);
            *(float2*)&O[(size_t)(b * 2048 + rowg + 8) * 1024 + cc] =
                make_float2(oacc[mt][nt][2] * l1, oacc[mt][nt][3] * l1);
        }
    }
}

// ---------------------------------------------------------------------------
// residual + LayerNorm
// ---------------------------------------------------------------------------
__global__ void __launch_bounds__(256) ln_kernel(
    const float* __restrict__ Y, const float* __restrict__ R,
    const float* __restrict__ g, const float* __restrict__ bt,
    float* __restrict__ out)
{
    __shared__ float red[2][8];
    int row = blockIdx.x;
    int tid = threadIdx.x;
    int lane = tid & 31, wid = tid >> 5;

    float4 y4 = ((const float4*)(Y + (size_t)row * 1024))[tid];
    float4 r4 = ((const float4*)(R + (size_t)row * 1024))[tid];
    float x0 = y4.x + r4.x, x1 = y4.y + r4.y, x2 = y4.z + r4.z, x3 = y4.w + r4.w;

    float sum = x0 + x1 + x2 + x3;
    float sq  = x0 * x0 + x1 * x1 + x2 * x2 + x3 * x3;
#pragma unroll
    for (int off = 16; off > 0; off >>= 1) {
        sum += __shfl_xor_sync(0xffffffff, sum, off);
        sq  += __shfl_xor_sync(0xffffffff, sq,  off);
    }
    if (lane == 0) { red[0][wid] = sum; red[1][wid] = sq; }
    __syncthreads();
    if (tid == 0) {
        float ts = 0.f, tq = 0.f;
#pragma unroll
        for (int w = 0; w < 8; w++) { ts += red[0][w]; tq += red[1][w]; }
        red[0][0] = ts; red[1][0] = tq;
    }
    __syncthreads();
    float mu  = red[0][0] * (1.f / 1024.f);
    float var = red[1][0] * (1.f / 1024.f) - mu * mu;
    float rstd = rsqrtf(var + 1e-6f);

    float4 g4 = ((const float4*)g)[tid];
    float4 b4 = ((const float4*)bt)[tid];
    float4 o;
    o.x = (x0 - mu) * rstd * g4.x + b4.x;
    o.y = (x1 - mu) * rstd * g4.y + b4.y;
    o.z = (x2 - mu) * rstd * g4.z + b4.z;
    o.w = (x3 - mu) * rstd * g4.w + b4.w;
    ((float4*)(out + (size_t)row * 1024))[tid] = o;
}

// ---------------------------------------------------------------------------
extern "C" void kernel_launch(void* const* d_in, const int* in_sizes, int n_in,
                              void* d_out, int out_size)
{
    const float* query = (const float*)d_in[0];
    const float* key   = (const float*)d_in[1];
    const float* value = (const float*)d_in[2];
    const int*   mask  = (const int*)d_in[3];
    const float* w_qs  = (const float*)d_in[4];
    const float* w_ks  = (const float*)d_in[5];
    const float* w_vs  = (const float*)d_in[6];
    const float* w_out = (const float*)d_in[7];
    const float* ln_g  = (const float*)d_in[8];
    const float* ln_b  = (const float*)d_in[9];
    float* out = (float*)d_out;

    __nv_bfloat16 *q, *k, *v;
    float *attn, *y;
    cudaGetSymbolAddress((void**)&q,    g_q);
    cudaGetSymbolAddress((void**)&k,    g_k);
    cudaGetSymbolAddress((void**)&v,    g_v);
    cudaGetSymbolAddress((void**)&attn, g_attn);
    cudaGetSymbolAddress((void**)&y,    g_y);

    cudaFuncSetAttribute(gemm_proj,
                         cudaFuncAttributeMaxDynamicSharedMemorySize, GEMM_SMEM);
    cudaFuncSetAttribute(gemm_out,
                         cudaFuncAttributeMaxDynamicSharedMemorySize, GEMM_SMEM);
    cudaFuncSetAttribute(attn_tc,
                         cudaFuncAttributeMaxDynamicSharedMemorySize, ATTN_SMEM);

    gemm_proj<<<dim3(8, 64, 3), 128, GEMM_SMEM>>>(
        query, key, value, w_qs, w_ks, w_vs, q, k, v);

    attn_tc<<<dim3(16, 16, 4), 128, ATTN_SMEM>>>(q, k, v, mask, attn);

    gemm_out<<<dim3(8, 64), 128, GEMM_SMEM>>>(attn, w_out, y);

    ln_kernel<<<8192, 256>>>(y, query, ln_g, ln_b, out);
}

// round 17
// speedup vs baseline: 1.1372x; 1.0598x over previous
#include <cuda_runtime.h>
#include <cuda_bf16.h>

// ---------------------------------------------------------------------------
// MultiHeadedAttention: B=4, S=2048, D_MODEL=1024, H=16, DK=DV=64
// Round 17: mask bit-packing (67 MB int32 -> 2 MB bits; attn mask LDG
//           traffic /32). GEMMs (64x64 warp tiles) + attn datapath = R16.
// ---------------------------------------------------------------------------

#define NEGV (-1e9f)
#define MINIT (-1e38f)

__device__ __nv_bfloat16 g_q[4 * 16 * 2048 * 64];
__device__ __nv_bfloat16 g_k[4 * 16 * 2048 * 64];
__device__ __nv_bfloat16 g_v[4 * 16 * 2048 * 64];   // V^T per head [B,H,64,2048]
__device__ float g_attn[8192 * 1024];
__device__ float g_y[8192 * 1024];
__device__ unsigned g_maskp[4 * 2048 * 64];          // packed mask bits

__device__ __forceinline__ void mma_tf32(float c[4], const unsigned a[4],
                                         const unsigned b[2]) {
    asm volatile(
        "mma.sync.aligned.m16n8k8.row.col.f32.tf32.tf32.f32 "
        "{%0,%1,%2,%3}, {%4,%5,%6,%7}, {%8,%9}, {%0,%1,%2,%3};"
        : "+f"(c[0]), "+f"(c[1]), "+f"(c[2]), "+f"(c[3])
        : "r"(a[0]), "r"(a[1]), "r"(a[2]), "r"(a[3]), "r"(b[0]), "r"(b[1]));
}

__device__ __forceinline__ void mma_bf16(float c[4], const unsigned a[4],
                                         const unsigned b[2]) {
    asm volatile(
        "mma.sync.aligned.m16n8k16.row.col.f32.bf16.bf16.f32 "
        "{%0,%1,%2,%3}, {%4,%5,%6,%7}, {%8,%9}, {%0,%1,%2,%3};"
        : "+f"(c[0]), "+f"(c[1]), "+f"(c[2]), "+f"(c[3])
        : "r"(a[0]), "r"(a[1]), "r"(a[2]), "r"(a[3]), "r"(b[0]), "r"(b[1]));
}

__device__ __forceinline__ void ldsm4(unsigned& r0, unsigned& r1,
                                      unsigned& r2, unsigned& r3,
                                      const void* p) {
    unsigned a = (unsigned)__cvta_generic_to_shared(p);
    asm volatile(
        "ldmatrix.sync.aligned.m8n8.x4.shared.b16 {%0,%1,%2,%3}, [%4];"
        : "=r"(r0), "=r"(r1), "=r"(r2), "=r"(r3) : "r"(a));
}

__device__ __forceinline__ float ex2(float x) {
    float y;
    asm("ex2.approx.f32 %0, %1;" : "=f"(y) : "f"(x));
    return y;
}

__device__ __forceinline__ unsigned pack_bf16(float lo, float hi) {
    unsigned u;
    asm("cvt.rn.bf16x2.f32 %0, %1, %2;" : "=r"(u) : "f"(hi), "f"(lo));
    return u;
}

__device__ __forceinline__ void cpa16(void* sptr, const void* gptr) {
    unsigned s = (unsigned)__cvta_generic_to_shared(sptr);
    asm volatile("cp.async.cg.shared.global [%0], [%1], 16;"
                 :: "r"(s), "l"(gptr));
}
#define CP_COMMIT() asm volatile("cp.async.commit_group;")
#define CP_WAIT1()  asm volatile("cp.async.wait_group 1;")
#define CP_WAIT0()  asm volatile("cp.async.wait_group 0;")

// ---------------------------------------------------------------------------
// mask bit-packing: each thread packs 32 int32 -> 1 uint32
// total words = 4*2048*2048/32 = 524288
// ---------------------------------------------------------------------------
__global__ void __launch_bounds__(256) mask_pack(
    const int* __restrict__ mask, unsigned* __restrict__ mp)
{
    int w = blockIdx.x * 256 + threadIdx.x;
    const int* src = mask + (size_t)w * 32;
    unsigned bits = 0;
#pragma unroll
    for (int i = 0; i < 32; i += 4) {
        int4 m = *(const int4*)&src[i];
        bits |= (m.x ? 1u : 0u) << i;
        bits |= (m.y ? 1u : 0u) << (i + 1);
        bits |= (m.z ? 1u : 0u) << (i + 2);
        bits |= (m.w ? 1u : 0u) << (i + 3);
    }
    mp[w] = bits;
}

// ---------------------------------------------------------------------------
// tf32 GEMM body (R16): 128x128 tile, k-tile 32, 128 threads (4 warps,
// 64x64 warp tiles), cp.async 3-stage pipeline.
// ---------------------------------------------------------------------------
#define GA_SZ (128 * 36)
#define GB_SZ (32 * 132)
#define GSTAGES 3
#define GEMM_SMEM (GSTAGES * (GA_SZ + GB_SZ) * 4)

__device__ __forceinline__ void gemm_body(
    const float* __restrict__ A, const float* __restrict__ B,
    void* __restrict__ Cv, int M, int N, int K, int mode,
    unsigned* As, unsigned* Bs)
{
    int tid = threadIdx.x;
    int wid = tid >> 5, lane = tid & 31;
    int r = lane >> 2, c = lane & 3, g = lane >> 2;
    int m0 = blockIdx.y * 128, n0 = blockIdx.x * 128;
    int wm = (wid & 1) * 64, wn = (wid >> 1) * 64;

    int arow[8], acol[8], brow[8], bcol[8];
#pragma unroll
    for (int i = 0; i < 8; i++) {
        int lin = tid + i * 128;
        arow[i] = lin >> 3;  acol[i] = (lin & 7) << 2;
        brow[i] = lin >> 5;  bcol[i] = (lin & 31) << 2;
    }

    float acc[4][8][4];
#pragma unroll
    for (int mt = 0; mt < 4; mt++)
#pragma unroll
        for (int nt = 0; nt < 8; nt++)
#pragma unroll
            for (int i = 0; i < 4; i++) acc[mt][nt][i] = 0.f;

    int ktiles = K >> 5;

#pragma unroll
    for (int st = 0; st < 2; st++) {
        int k0 = st * 32;
        unsigned* Asx = As + st * GA_SZ;
        unsigned* Bsx = Bs + st * GB_SZ;
#pragma unroll
        for (int i = 0; i < 8; i++) {
            cpa16(&Asx[arow[i] * 36 + acol[i]],
                  &A[(size_t)(m0 + arow[i]) * K + k0 + acol[i]]);
            cpa16(&Bsx[brow[i] * 132 + bcol[i]],
                  &B[(size_t)(k0 + brow[i]) * N + n0 + bcol[i]]);
        }
        CP_COMMIT();
    }

    for (int it = 0; it < ktiles; it++) {
        CP_WAIT1();
        __syncthreads();

        if (it + 2 < ktiles) {
            int st = (it + 2) % GSTAGES;
            int k0 = (it + 2) * 32;
            unsigned* Asx = As + st * GA_SZ;
            unsigned* Bsx = Bs + st * GB_SZ;
#pragma unroll
            for (int i = 0; i < 8; i++) {
                cpa16(&Asx[arow[i] * 36 + acol[i]],
                      &A[(size_t)(m0 + arow[i]) * K + k0 + acol[i]]);
                cpa16(&Bsx[brow[i] * 132 + bcol[i]],
                      &B[(size_t)(k0 + brow[i]) * N + n0 + bcol[i]]);
            }
        }
        CP_COMMIT();

        const unsigned* Asx = As + (it % GSTAGES) * GA_SZ;
        const unsigned* Bsx = Bs + (it % GSTAGES) * GB_SZ;
#pragma unroll
        for (int ks = 0; ks < 4; ks++) {
            int k8 = ks * 8;
            unsigned ua[4][4], ub[8][2];
#pragma unroll
            for (int mt = 0; mt < 4; mt++) {
                int rr = wm + mt * 16 + r;
                ua[mt][0] = Asx[rr * 36 + k8 + c];
                ua[mt][1] = Asx[(rr + 8) * 36 + k8 + c];
                ua[mt][2] = Asx[rr * 36 + k8 + c + 4];
                ua[mt][3] = Asx[(rr + 8) * 36 + k8 + c + 4];
            }
#pragma unroll
            for (int nt = 0; nt < 8; nt++) {
                int cn = wn + nt * 8 + g;
                ub[nt][0] = Bsx[(k8 + c) * 132 + cn];
                ub[nt][1] = Bsx[(k8 + c + 4) * 132 + cn];
            }
#pragma unroll
            for (int mt = 0; mt < 4; mt++)
#pragma unroll
                for (int nt = 0; nt < 8; nt++)
                    mma_tf32(acc[mt][nt], ua[mt], ub[nt]);
        }
        __syncthreads();
    }

#pragma unroll
    for (int mt = 0; mt < 4; mt++) {
#pragma unroll
        for (int nt = 0; nt < 8; nt++) {
            int rr = m0 + wm + mt * 16 + r;
            int cc = n0 + wn + nt * 8 + 2 * c;
            float* a4 = acc[mt][nt];
            if (mode == 0) {
                float* C = (float*)Cv;
                *(float2*)&C[(size_t)rr * N + cc] = make_float2(a4[0], a4[1]);
                *(float2*)&C[(size_t)(rr + 8) * N + cc] = make_float2(a4[2], a4[3]);
            } else if (mode == 1) {
                __nv_bfloat16* C = (__nv_bfloat16*)Cv;
                int b = rr >> 11, s = rr & 2047;
                int h = cc >> 6, d = cc & 63;
                size_t idx = (((size_t)(b * 16 + h) * 2048 + s) << 6) + d;
                *(__nv_bfloat162*)&C[idx] = __floats2bfloat162_rn(a4[0], a4[1]);
                int b2 = (rr + 8) >> 11, s2 = (rr + 8) & 2047;
                size_t idx2 = (((size_t)(b2 * 16 + h) * 2048 + s2) << 6) + d;
                *(__nv_bfloat162*)&C[idx2] = __floats2bfloat162_rn(a4[2], a4[3]);
            } else {  // bf16 V^T [B,H,64,2048]
                __nv_bfloat16* C = (__nv_bfloat16*)Cv;
                int b = rr >> 11, s = rr & 2047;
                int h = cc >> 6, d = cc & 63;
                size_t base = ((size_t)(b * 16 + h) * 64 + d) * 2048;
                C[base + s] = __float2bfloat16_rn(a4[0]);
                C[base + 2048 + s] = __float2bfloat16_rn(a4[1]);
                int b2 = (rr + 8) >> 11, s2 = (rr + 8) & 2047;
                size_t base2 = ((size_t)(b2 * 16 + h) * 64 + d) * 2048;
                C[base2 + s2] = __float2bfloat16_rn(a4[2]);
                C[base2 + 2048 + s2] = __float2bfloat16_rn(a4[3]);
            }
        }
    }
}

__global__ void __launch_bounds__(128, 2) gemm_proj(
    const float* __restrict__ Aq, const float* __restrict__ Ak,
    const float* __restrict__ Av,
    const float* __restrict__ Bq, const float* __restrict__ Bk,
    const float* __restrict__ Bv,
    __nv_bfloat16* q, __nv_bfloat16* k, __nv_bfloat16* v)
{
    extern __shared__ unsigned gsm[];
    int z = blockIdx.z;
    const float* A = (z == 0) ? Aq : (z == 1) ? Ak : Av;
    const float* B = (z == 0) ? Bq : (z == 1) ? Bk : Bv;
    void* C = (z == 0) ? (void*)q : (z == 1) ? (void*)k : (void*)v;
    int mode = (z == 2) ? 2 : 1;
    gemm_body(A, B, C, 8192, 1024, 1024, mode, gsm, gsm + GSTAGES * GA_SZ);
}

__global__ void __launch_bounds__(128, 2) gemm_out(
    const float* __restrict__ A, const float* __restrict__ B,
    float* __restrict__ C)
{
    extern __shared__ unsigned gsm[];
    gemm_body(A, B, C, 8192, 1024, 1024, 0, gsm, gsm + GSTAGES * GA_SZ);
}

// ---------------------------------------------------------------------------
// Flash attention (R14 datapath + packed mask): bf16 mma + ldmatrix,
// cp.async K/V double-buffer. grid (S/128, H, B), 128 threads.
// SMEM bf16 stride 72: Qs[128] K0[64] K1[64] V0[64] V1[64] Ps[128] = 72 KB
// ---------------------------------------------------------------------------
#define SQ 72
#define ATTN_SMEM ((128 + 2 * 64 + 2 * 64 + 128) * SQ * 2)

__global__ void __launch_bounds__(128, 2) attn_tc(
    const __nv_bfloat16* __restrict__ Q, const __nv_bfloat16* __restrict__ Kg,
    const __nv_bfloat16* __restrict__ Vt, const unsigned* __restrict__ Mp,
    float* __restrict__ O)
{
    extern __shared__ __align__(16) __nv_bfloat16 smb[];
    __nv_bfloat16* Qs = smb;                       // 128 x 72
    __nv_bfloat16* Kst[2] = {Qs + 128 * SQ, Qs + (128 + 64) * SQ};
    __nv_bfloat16* Vst[2] = {Qs + (128 + 128) * SQ, Qs + (128 + 192) * SQ};
    __nv_bfloat16* Ps = Qs + (128 + 256) * SQ;     // 128 x 72

    int tid = threadIdx.x;
    int wid = tid >> 5, lane = tid & 31;
    int r = lane >> 2, c = lane & 3;
    int qt = blockIdx.x, h = blockIdx.y, b = blockIdx.z;
    int qbase = qt * 128;
    int wm = wid * 32;
    int c2 = 2 * c;

    const float SC = 0.125f * 1.44269504088896f;

    const __nv_bfloat16* qp  = Q  + (((size_t)(b * 16 + h) * 2048 + qbase) << 6);
    const __nv_bfloat16* kp0 = Kg + (((size_t)(b * 16 + h) * 2048) << 6);
    const __nv_bfloat16* vt0 = Vt + ((size_t)(b * 16 + h) * 64) * 2048;

    // packed-mask row pointers: 64 words per row of 2048 bits
    const unsigned* mrowp[2][2];
#pragma unroll
    for (int mt = 0; mt < 2; mt++)
#pragma unroll
        for (int hf = 0; hf < 2; hf++)
            mrowp[mt][hf] = Mp +
                ((size_t)(b * 2048 + qbase + wm + mt * 16 + r + hf * 8)) * 64;

    int srow = tid >> 3, sch = (tid & 7) << 3;

    // stage Q tile + first K/V tile
#pragma unroll
    for (int i = 0; i < 8; i++) {
        int lin = tid + i * 128;
        int row = lin >> 3, ch = (lin & 7) << 3;
        *(uint4*)&Qs[row * SQ + ch] = *(const uint4*)&qp[row * 64 + ch];
    }
#pragma unroll
    for (int i = 0; i < 4; i++) {
        int row = srow + i * 16;
        cpa16(&Kst[0][row * SQ + sch], &kp0[(size_t)row * 64 + sch]);
        cpa16(&Vst[0][row * SQ + sch], &vt0[(size_t)row * 2048 + sch]);
    }
    CP_COMMIT();

    int la_row = lane & 15;
    int la_col = (lane >> 4) << 3;
    int lb_row = ((lane >> 4) << 3) + (lane & 7);
    int lb_col = ((lane >> 3) & 1) << 3;

    float m_[2][2], l_[2][2];
#pragma unroll
    for (int mt = 0; mt < 2; mt++)
#pragma unroll
        for (int hf = 0; hf < 2; hf++) { m_[mt][hf] = MINIT; l_[mt][hf] = 0.f; }

    float oacc[2][8][4];
#pragma unroll
    for (int mt = 0; mt < 2; mt++)
#pragma unroll
        for (int nt = 0; nt < 8; nt++)
#pragma unroll
            for (int i = 0; i < 4; i++) oacc[mt][nt][i] = 0.f;

    for (int it = 0; it < 32; it++) {
        int kb = it * 64;
        CP_WAIT0();
        __syncthreads();

        if (it + 1 < 32) {
            int kb2 = kb + 64;
            __nv_bfloat16* Kn = Kst[(it + 1) & 1];
            __nv_bfloat16* Vn = Vst[(it + 1) & 1];
#pragma unroll
            for (int i = 0; i < 4; i++) {
                int row = srow + i * 16;
                cpa16(&Kn[row * SQ + sch], &kp0[(size_t)(kb2 + row) * 64 + sch]);
                cpa16(&Vn[row * SQ + sch], &vt0[(size_t)row * 2048 + kb2 + sch]);
            }
        }
        CP_COMMIT();

        const __nv_bfloat16* Ks = Kst[it & 1];
        const __nv_bfloat16* Vs = Vst[it & 1];

        // ---- S = Q K^T ----
        float sacc[2][8][4];
#pragma unroll
        for (int mt = 0; mt < 2; mt++)
#pragma unroll
            for (int nt = 0; nt < 8; nt++)
#pragma unroll
                for (int i = 0; i < 4; i++) sacc[mt][nt][i] = 0.f;

#pragma unroll
        for (int ks = 0; ks < 4; ks++) {
            int k16 = ks * 16;
            unsigned ua[2][4], ubs[8][2];
#pragma unroll
            for (int mt = 0; mt < 2; mt++)
                ldsm4(ua[mt][0], ua[mt][1], ua[mt][2], ua[mt][3],
                      &Qs[(wm + mt * 16 + la_row) * SQ + k16 + la_col]);
#pragma unroll
            for (int nt2 = 0; nt2 < 4; nt2++) {
                unsigned r0, r1, r2, r3;
                ldsm4(r0, r1, r2, r3,
                      &Ks[(nt2 * 16 + lb_row) * SQ + k16 + lb_col]);
                ubs[nt2 * 2][0] = r0;  ubs[nt2 * 2][1] = r1;
                ubs[nt2 * 2 + 1][0] = r2;  ubs[nt2 * 2 + 1][1] = r3;
            }
#pragma unroll
            for (int mt = 0; mt < 2; mt++)
#pragma unroll
                for (int nt = 0; nt < 8; nt++)
                    mma_bf16(sacc[mt][nt], ua[mt], ubs[nt]);
        }

        // ---- mask (packed bits) + online softmax (log2 domain) ----
#pragma unroll
        for (int mt = 0; mt < 2; mt++) {
            // 64 mask bits per row for this k-block: two words each row half
            uint2 w0 = *(const uint2*)&mrowp[mt][0][it * 2];
            uint2 w1 = *(const uint2*)&mrowp[mt][1][it * 2];
            float mx0 = m_[mt][0], mx1 = m_[mt][1];
#pragma unroll
            for (int nt = 0; nt < 8; nt++) {
                unsigned wa = (nt < 4) ? w0.x : w0.y;
                unsigned wb = (nt < 4) ? w1.x : w1.y;
                int sh = (nt & 3) * 8 + c2;
                float s0 = ((wa >> sh) & 1u) ? sacc[mt][nt][0] * SC : NEGV;
                float s1 = ((wa >> (sh + 1)) & 1u) ? sacc[mt][nt][1] * SC : NEGV;
                float s2 = ((wb >> sh) & 1u) ? sacc[mt][nt][2] * SC : NEGV;
                float s3 = ((wb >> (sh + 1)) & 1u) ? sacc[mt][nt][3] * SC : NEGV;
                sacc[mt][nt][0] = s0; sacc[mt][nt][1] = s1;
                sacc[mt][nt][2] = s2; sacc[mt][nt][3] = s3;
                mx0 = fmaxf(mx0, fmaxf(s0, s1));
                mx1 = fmaxf(mx1, fmaxf(s2, s3));
            }
            mx0 = fmaxf(mx0, __shfl_xor_sync(0xffffffffu, mx0, 1));
            mx0 = fmaxf(mx0, __shfl_xor_sync(0xffffffffu, mx0, 2));
            mx1 = fmaxf(mx1, __shfl_xor_sync(0xffffffffu, mx1, 1));
            mx1 = fmaxf(mx1, __shfl_xor_sync(0xffffffffu, mx1, 2));

            float al0 = ex2(m_[mt][0] - mx0);
            float al1 = ex2(m_[mt][1] - mx1);
            float sum0 = 0.f, sum1 = 0.f;
            int rr = wm + mt * 16 + r;
#pragma unroll
            for (int nt = 0; nt < 8; nt++) {
                float p0 = ex2(sacc[mt][nt][0] - mx0);
                float p1 = ex2(sacc[mt][nt][1] - mx0);
                float p2 = ex2(sacc[mt][nt][2] - mx1);
                float p3 = ex2(sacc[mt][nt][3] - mx1);
                sum0 += p0 + p1;
                sum1 += p2 + p3;
                *(unsigned*)&Ps[rr * SQ + nt * 8 + c2] = pack_bf16(p0, p1);
                *(unsigned*)&Ps[(rr + 8) * SQ + nt * 8 + c2] = pack_bf16(p2, p3);
            }
            sum0 += __shfl_xor_sync(0xffffffffu, sum0, 1);
            sum0 += __shfl_xor_sync(0xffffffffu, sum0, 2);
            sum1 += __shfl_xor_sync(0xffffffffu, sum1, 1);
            sum1 += __shfl_xor_sync(0xffffffffu, sum1, 2);

            m_[mt][0] = mx0; m_[mt][1] = mx1;
            l_[mt][0] = l_[mt][0] * al0 + sum0;
            l_[mt][1] = l_[mt][1] * al1 + sum1;
#pragma unroll
            for (int nt = 0; nt < 8; nt++) {
                oacc[mt][nt][0] *= al0; oacc[mt][nt][1] *= al0;
                oacc[mt][nt][2] *= al1; oacc[mt][nt][3] *= al1;
            }
        }
        __syncwarp();   // Ps rows are warp-private

        // ---- O += P V ----
#pragma unroll
        for (int ks = 0; ks < 4; ks++) {
            int k16 = ks * 16;
            unsigned ua[2][4], ubs[8][2];
#pragma unroll
            for (int mt = 0; mt < 2; mt++)
                ldsm4(ua[mt][0], ua[mt][1], ua[mt][2], ua[mt][3],
                      &Ps[(wm + mt * 16 + la_row) * SQ + k16 + la_col]);
#pragma unroll
            for (int nt2 = 0; nt2 < 4; nt2++) {
                unsigned r0, r1, r2, r3;
                ldsm4(r0, r1, r2, r3,
                      &Vs[(nt2 * 16 + lb_row) * SQ + k16 + lb_col]);
                ubs[nt2 * 2][0] = r0;  ubs[nt2 * 2][1] = r1;
                ubs[nt2 * 2 + 1][0] = r2;  ubs[nt2 * 2 + 1][1] = r3;
            }
#pragma unroll
            for (int mt = 0; mt < 2; mt++)
#pragma unroll
                for (int nt = 0; nt < 8; nt++)
                    mma_bf16(oacc[mt][nt], ua[mt], ubs[nt]);
        }
        __syncthreads();
    }

    // final normalize + write [B,S,H*64] fp32
#pragma unroll
    for (int mt = 0; mt < 2; mt++) {
        float l0 = 1.f / l_[mt][0];
        float l1 = 1.f / l_[mt][1];
        int rowg = qbase + wm + mt * 16 + r;
#pragma unroll
        for (int nt = 0; nt < 8; nt++) {
            int cc = h * 64 + nt * 8 + c2;
            *(float2*)&O[(size_t)(b * 2048 + rowg) * 1024 + cc] =
                make_float2(oacc[mt][nt][0] * l0, oacc[mt][nt][1] * l0);
            *(float2*)&O[(size_t)(b * 2048 + rowg + 8) * 1024 + cc] =
                make_float2(oacc[mt][nt][2] * l1, oacc[mt][nt][3] * l1);
        }
    }
}

// ---------------------------------------------------------------------------
// residual + LayerNorm
// ---------------------------------------------------------------------------
__global__ void __launch_bounds__(256) ln_kernel(
    const float* __restrict__ Y, const float* __restrict__ R,
    const float* __restrict__ g, const float* __restrict__ bt,
    float* __restrict__ out)
{
    __shared__ float red[2][8];
    int row = blockIdx.x;
    int tid = threadIdx.x;
    int lane = tid & 31, wid = tid >> 5;

    float4 y4 = ((const float4*)(Y + (size_t)row * 1024))[tid];
    float4 r4 = ((const float4*)(R + (size_t)row * 1024))[tid];
    float x0 = y4.x + r4.x, x1 = y4.y + r4.y, x2 = y4.z + r4.z, x3 = y4.w + r4.w;

    float sum = x0 + x1 + x2 + x3;
    float sq  = x0 * x0 + x1 * x1 + x2 * x2 + x3 * x3;
#pragma unroll
    for (int off = 16; off > 0; off >>= 1) {
        sum += __shfl_xor_sync(0xffffffff, sum, off);
        sq  += __shfl_xor_sync(0xffffffff, sq,  off);
    }
    if (lane == 0) { red[0][wid] = sum; red[1][wid] = sq; }
    __syncthreads();
    if (tid == 0) {
        float ts = 0.f, tq = 0.f;
#pragma unroll
        for (int w = 0; w < 8; w++) { ts += red[0][w]; tq += red[1][w]; }
        red[0][0] = ts; red[1][0] = tq;
    }
    __syncthreads();
    float mu  = red[0][0] * (1.f / 1024.f);
    float var = red[1][0] * (1.f / 1024.f) - mu * mu;
    float rstd = rsqrtf(var + 1e-6f);

    float4 g4 = ((const float4*)g)[tid];
    float4 b4 = ((const float4*)bt)[tid];
    float4 o;
    o.x = (x0 - mu) * rstd * g4.x + b4.x;
    o.y = (x1 - mu) * rstd * g4.y + b4.y;
    o.z = (x2 - mu) * rstd * g4.z + b4.z;
    o.w = (x3 - mu) * rstd * g4.w + b4.w;
    ((float4*)(out + (size_t)row * 1024))[tid] = o;
}

// ---------------------------------------------------------------------------
extern "C" void kernel_launch(void* const* d_in, const int* in_sizes, int n_in,
                              void* d_out, int out_size)
{
    const float* query = (const float*)d_in[0];
    const float* key   = (const float*)d_in[1];
    const float* value = (const float*)d_in[2];
    const int*   mask  = (const int*)d_in[3];
    const float* w_qs  = (const float*)d_in[4];
    const float* w_ks  = (const float*)d_in[5];
    const float* w_vs  = (const float*)d_in[6];
    const float* w_out = (const float*)d_in[7];
    const float* ln_g  = (const float*)d_in[8];
    const float* ln_b  = (const float*)d_in[9];
    float* out = (float*)d_out;

    __nv_bfloat16 *q, *k, *v;
    float *attn, *y;
    unsigned* mp;
    cudaGetSymbolAddress((void**)&q,    g_q);
    cudaGetSymbolAddress((void**)&k,    g_k);
    cudaGetSymbolAddress((void**)&v,    g_v);
    cudaGetSymbolAddress((void**)&attn, g_attn);
    cudaGetSymbolAddress((void**)&y,    g_y);
    cudaGetSymbolAddress((void**)&mp,   g_maskp);

    cudaFuncSetAttribute(gemm_proj,
                         cudaFuncAttributeMaxDynamicSharedMemorySize, GEMM_SMEM);
    cudaFuncSetAttribute(gemm_out,
                         cudaFuncAttributeMaxDynamicSharedMemorySize, GEMM_SMEM);
    cudaFuncSetAttribute(attn_tc,
                         cudaFuncAttributeMaxDynamicSharedMemorySize, ATTN_SMEM);

    mask_pack<<<2048, 256>>>(mask, mp);

    gemm_proj<<<dim3(8, 64, 3), 128, GEMM_SMEM>>>(
        query, key, value, w_qs, w_ks, w_vs, q, k, v);

    attn_tc<<<dim3(16, 16, 4), 128, ATTN_SMEM>>>(q, k, v, mp, attn);

    gemm_out<<<dim3(8, 64), 128, GEMM_SMEM>>>(attn, w_out, y);

    ln_kernel<<<8192, 256>>>(y, query, ln_g, ln_b, out);
}